// round 4
// baseline (speedup 1.0000x reference)
#include <cuda_runtime.h>

#define DEV __device__ __forceinline__

constexpr int B    = 8;
constexpr int N    = 8192;
constexpr int M    = 2500;
constexpr int SPP  = 250;    // M / P(=10)

// chamfer decomposition — fine chunks for occupancy & balance
constexpr int QPB    = 512;                 // queries per block (4 x 128)
constexpr int GX_P   = (M + QPB - 1) / QPB; // 5
constexpr int NCHUNK = 16;                  // gt candidate chunks (512 pts each)
constexpr int CP_P   = N / NCHUNK / 2;      // 256 packs
constexpr int GX_G   = N / QPB;             // 16
constexpr int MCHUNK = 5;                   // pred candidate chunks (500 pts each)
constexpr int CP_G   = M / MCHUNK / 2;      // 250 packs
constexpr int NBLK_P = GX_P * B * NCHUNK;   // 640
constexpr int NBLK_G = GX_G * B * MCHUNK;   // 640
constexpr int NBLK_F = 20 * B;              // 160 fff blocks
constexpr int NBLK_1 = NBLK_P + NBLK_G + NBLK_F;  // 1440

constexpr int FB_P   = (B * M + 511) / 512; // 40
constexpr int FB_G   = (B * N) / 512;       // 128

// Partial result arrays — every slot written unconditionally, no init needed.
__device__ float g_partP[NCHUNK * B * M];
__device__ float g_partG[MCHUNK * B * N];
__device__ float g_fffp[NBLK_F * 11];
__device__ float g_sum2[FB_P + FB_G];

// ---- packed fp32x2 helpers ----
DEV unsigned long long pack2(float lo, float hi) {
    unsigned long long r;
    asm("mov.b64 %0, {%1, %2};" : "=l"(r) : "f"(lo), "f"(hi));
    return r;
}
DEV void unpack2(unsigned long long v, float& lo, float& hi) {
    asm("mov.b64 {%0, %1}, %2;" : "=f"(lo), "=f"(hi) : "l"(v));
}
DEV unsigned long long fma2(unsigned long long a, unsigned long long b, unsigned long long c) {
    unsigned long long d;
    asm("fma.rn.f32x2 %0, %1, %2, %3;" : "=l"(d) : "l"(a), "l"(b), "l"(c));
    return d;
}

DEV float blockReduceSum(float v) {
    __shared__ float sred[32];
    #pragma unroll
    for (int o = 16; o > 0; o >>= 1) v += __shfl_down_sync(0xffffffffu, v, o);
    int lane = threadIdx.x & 31, w = threadIdx.x >> 5;
    if (lane == 0) sred[w] = v;
    __syncthreads();
    int nw = (blockDim.x + 31) >> 5;
    v = (threadIdx.x < (unsigned)nw) ? sred[threadIdx.x] : 0.0f;
    if (w == 0) {
        #pragma unroll
        for (int o = 16; o > 0; o >>= 1) v += __shfl_down_sync(0xffffffffu, v, o);
    }
    __syncthreads();
    return v;  // valid in thread 0
}

// ================= K1: mega kernel — chamfer chunks + fff partials =================
__global__ void __launch_bounds__(128) k_mega(const float* __restrict__ pred,
                                              const float* __restrict__ gt,
                                              const float* __restrict__ fff) {
    int bid = blockIdx.x;
    int tid = threadIdx.x;

    if (bid >= NBLK_P + NBLK_G) {
        // ---------------- fff partial-sums block ----------------
        int fb = bid - (NBLK_P + NBLK_G);
        int b  = fb / 20;
        int m  = (fb % 20) * 128 + tid;
        float v[11];
        #pragma unroll
        for (int i = 0; i < 11; i++) v[i] = 0.0f;
        if (m < M) {
            int idx = (b * M + m) * 3;
            float E = fff[idx], F = fff[idx + 1], G = fff[idx + 2];
            float A2  = fmaxf(E * G - F * F, 0.0f);
            float A   = sqrtf(A2);
            float inv = 1.0f / (A2 + 1e-20f);
            v[0] = E;        v[1] = G;        v[2] = inv;
            v[3] = E * inv;  v[4] = E * E * inv;
            v[5] = G * inv;  v[6] = G * G * inv;
            v[7] = F * F * inv;
            float d = E - G; v[8] = d * d * inv;
            if ((b & 1) == 0) {
                int idx2 = ((b + 1) * M + m) * 3;
                float E2 = fff[idx2], F2 = fff[idx2 + 1], G2 = fff[idx2 + 2];
                float dE = E - E2, dF = F - F2, dG = G - G2;
                v[9] = dE * dE + 2.0f * dF * dF + dG * dG;
            }
            v[10] = A;
        }
        #pragma unroll
        for (int k = 0; k < 11; k++) {
            float s = blockReduceSum(v[k]);
            if (tid == 0) g_fffp[fb * 11 + k] = s;
        }
        return;
    }

    // ---------------- chamfer chunk block ----------------
    __shared__ ulonglong2 sc[2 * CP_P];  // 256 packs max -> 8KB

    const float* qb;
    const float* cb;
    float* outp;
    int npacks, q0, qlim;

    if (bid < NBLK_P) {
        int cx = bid % GX_P;
        int b  = (bid / GX_P) & 7;
        int ch = bid / (GX_P * B);          // [0,16)
        qb = pred + (size_t)b * M * 3;
        cb = gt   + (size_t)(b * N + ch * (2 * CP_P)) * 3;
        outp = g_partP + ch * (B * M) + b * M;
        npacks = CP_P; q0 = cx * QPB; qlim = M;
    } else {
        int gid = bid - NBLK_P;
        int cx = gid & (GX_G - 1);
        int b  = (gid >> 4) & 7;
        int ch = gid >> 7;                  // [0,5)
        qb = gt   + (size_t)b * N * 3;
        cb = pred + (size_t)(b * M + ch * (2 * CP_G)) * 3;
        outp = g_partG + ch * (B * N) + b * N;
        npacks = CP_G; q0 = cx * QPB; qlim = N;
    }

    // stage candidate pairs, pre-packed for FFMA2
    for (int j = tid; j < npacks; j += 128) {
        const float* g = cb + 6 * j;
        float x0 = g[0], y0 = g[1], z0 = g[2];
        float x1 = g[3], y1 = g[4], z1 = g[5];
        ulonglong2 u0, u1;
        u0.x = pack2(x0, x1);
        u0.y = pack2(y0, y1);
        u1.x = pack2(z0, z1);
        u1.y = pack2(x0 * x0 + y0 * y0 + z0 * z0,
                     x1 * x1 + y1 * y1 + z1 * z1);
        sc[2 * j]     = u0;
        sc[2 * j + 1] = u1;
    }

    // 4 queries per thread
    unsigned long long npx[4], npy[4], npz[4];
    float mn0[4], mn1[4];
    int   mq[4];
    bool  val[4];
    #pragma unroll
    for (int q = 0; q < 4; q++) {
        int m = q0 + q * 128 + tid;
        mq[q] = m; val[q] = (m < qlim);
        float px = 0.f, py = 0.f, pz = 0.f;
        if (val[q]) {
            const float* p = qb + (size_t)m * 3;
            px = p[0]; py = p[1]; pz = p[2];
        }
        npx[q] = pack2(-2.f * px, -2.f * px);
        npy[q] = pack2(-2.f * py, -2.f * py);
        npz[q] = pack2(-2.f * pz, -2.f * pz);
        mn0[q] = 3.4e38f; mn1[q] = 3.4e38f;
    }
    __syncthreads();

    #pragma unroll 2
    for (int j = 0; j < npacks; j++) {
        ulonglong2 u0 = sc[2 * j];
        ulonglong2 u1 = sc[2 * j + 1];
        #pragma unroll
        for (int q = 0; q < 4; q++) {
            unsigned long long t = fma2(u0.x, npx[q], u1.y);
            t = fma2(u0.y, npy[q], t);
            t = fma2(u1.x, npz[q], t);
            float lo, hi; unpack2(t, lo, hi);
            mn0[q] = fminf(mn0[q], lo);
            mn1[q] = fminf(mn1[q], hi);
        }
    }

    #pragma unroll
    for (int q = 0; q < 4; q++) {
        if (val[q]) outp[mq[q]] = fminf(mn0[q], mn1[q]);
    }
}

// ================= K2: finish — min over chunks, add norms, partial sums =========
__global__ void __launch_bounds__(512) k_finish(const float* __restrict__ pred,
                                                const float* __restrict__ gt) {
    int bid = blockIdx.x;
    int tid = threadIdx.x;
    float d = 0.0f;
    if (bid < FB_P) {
        int qi = bid * 512 + tid;          // [0, B*M)
        if (qi < B * M) {
            float f = g_partP[qi];
            #pragma unroll
            for (int ch = 1; ch < NCHUNK; ch++)
                f = fminf(f, g_partP[ch * (B * M) + qi]);
            const float* p = pred + (size_t)qi * 3;
            d = fmaxf(f + p[0] * p[0] + p[1] * p[1] + p[2] * p[2], 0.0f);
        }
    } else {
        int gi = (bid - FB_P) * 512 + tid;  // [0, B*N), exact
        float f = g_partG[gi];
        #pragma unroll
        for (int ch = 1; ch < MCHUNK; ch++)
            f = fminf(f, g_partG[ch * (B * N) + gi]);
        const float* g = gt + (size_t)gi * 3;
        d = fmaxf(f + g[0] * g[0] + g[1] * g[1] + g[2] * g[2], 0.0f);
    }
    float s = blockReduceSum(d);
    if (tid == 0) g_sum2[bid] = s;
}

// ================= K3: final combine =================
__global__ void __launch_bounds__(512) k_final(const float* __restrict__ A_gt,
                                               float* __restrict__ out) {
    int tid = threadIdx.x;
    __shared__ float sA[NBLK_F];
    __shared__ float acc[12];

    #pragma unroll
    for (int k = 0; k < 10; k++) {
        float v = (tid < NBLK_F) ? g_fffp[tid * 11 + k] : 0.0f;
        float s = blockReduceSum(v);
        if (tid == 0) acc[k] = s;
    }
    {
        float v = (tid < FB_P) ? g_sum2[tid] : 0.0f;
        float s = blockReduceSum(v);
        if (tid == 0) acc[10] = s;
        v = (tid < FB_G) ? g_sum2[FB_P + tid] : 0.0f;
        s = blockReduceSum(v);
        if (tid == 0) acc[11] = s;
    }
    if (tid < NBLK_F) sA[tid] = g_fffp[tid * 11 + 10];
    __syncthreads();

    if (tid == 0) {
        float BM = (float)(B * M);
        float L_chd = acc[10] / BM + acc[11] / (float)(B * N);
        float sE = acc[0], sG = acc[1], sInv = acc[2];
        float sEinv = acc[3], sE2inv = acc[4], sGinv = acc[5], sG2inv = acc[6];
        float sF2inv = acc[7], sStretch = acc[8], sMc = acc[9];
        float mE = sE / BM, mG = sG / BM;
        float L_E  = (sE2inv - 2.0f * mE * sEinv + mE * mE * sInv) / BM;
        float L_G  = (sG2inv - 2.0f * mG * sGinv + mG * mG * sInv) / BM;
        float L_F  = sF2inv  / BM;
        float L_st = sStretch / BM;
        float L_mc = sMc / (0.5f * BM);
        float L_ol = 0.0f;
        for (int b = 0; b < B; b++) {
            float at = 0.0f;
            for (int j = 0; j < 20; j++) at += sA[b * 20 + j];
            at *= (1.0f / (float)SPP);
            float r = fmaxf(at - A_gt[b], 0.0f);
            L_ol += r * r;
        }
        L_ol *= (1.0f / (float)B);
        out[0] = L_chd + L_mc + L_F + L_E + L_G + L_st + L_ol;
    }
}

extern "C" void kernel_launch(void* const* d_in, const int* in_sizes, int n_in,
                              void* d_out, int out_size) {
    (void)in_sizes; (void)n_in; (void)out_size;
    const float* pc_gt   = (const float*)d_in[0];
    const float* pc_pred = (const float*)d_in[1];
    const float* fffp    = (const float*)d_in[2];
    const float* A_gt    = (const float*)d_in[3];
    float* out = (float*)d_out;

    k_mega  <<<NBLK_1, 128>>>(pc_pred, pc_gt, fffp);
    k_finish<<<FB_P + FB_G, 512>>>(pc_pred, pc_gt);
    k_final <<<1, 512>>>(A_gt, out);
}

// round 5
// speedup vs baseline: 1.2394x; 1.2394x over previous
#include <cuda_runtime.h>

#define DEV __device__ __forceinline__

constexpr int B    = 8;
constexpr int N    = 8192;
constexpr int M    = 2500;
constexpr int SPP  = 250;    // M / P(=10)

// joint chamfer tiling: 512 pred queries x 512 gt candidates per block
constexpr int NP   = 5;             // pred chunks (5*512 = 2560 >= 2500)
constexpr int NG   = 16;            // gt chunks  (16*512 = 8192)
constexpr int CB   = 512;           // candidates per block
constexpr int CPK  = CB / 2;        // 256 candidate packs
constexpr int QB   = 512;           // queries per block (4 per thread x 128)
constexpr int NBLK_C = B * NP * NG; // 640
constexpr int NBLK_F = 20 * B;      // 160 fff blocks
constexpr int NBLK_1 = NBLK_C + NBLK_F;

constexpr int FB_P = (B * M + 511) / 512;   // 40
constexpr int FB_G = (B * N / 2) / 512;     // 64 (float2 per thread)

constexpr float BIG = 3.2e38f;

// Partials — every slot written unconditionally by owning blocks; no init kernel.
__device__ float  g_partP[NG * B * M];          // d^2 row-min partial per gt-chunk
__device__ float2 g_partG2[NP * (B * N / 2)];   // d^2 col-min partial per pred-chunk
__device__ float  g_fffp[NBLK_F * 11];
__device__ float  g_sum2[FB_P + FB_G];

// ---- packed fp32x2 helpers ----
DEV unsigned long long pack2(float lo, float hi) {
    unsigned long long r;
    asm("mov.b64 %0, {%1, %2};" : "=l"(r) : "f"(lo), "f"(hi));
    return r;
}
DEV void unpack2(unsigned long long v, float& lo, float& hi) {
    asm("mov.b64 {%0, %1}, %2;" : "=f"(lo), "=f"(hi) : "l"(v));
}
DEV unsigned long long fma2(unsigned long long a, unsigned long long b, unsigned long long c) {
    unsigned long long d;
    asm("fma.rn.f32x2 %0, %1, %2, %3;" : "=l"(d) : "l"(a), "l"(b), "l"(c));
    return d;
}
DEV unsigned long long add2(unsigned long long a, unsigned long long b) {
    unsigned long long d;
    asm("add.rn.f32x2 %0, %1, %2;" : "=l"(d) : "l"(a), "l"(b));
    return d;
}

DEV float blockReduceSum(float v) {
    __shared__ float sred[32];
    #pragma unroll
    for (int o = 16; o > 0; o >>= 1) v += __shfl_down_sync(0xffffffffu, v, o);
    int lane = threadIdx.x & 31, w = threadIdx.x >> 5;
    if (lane == 0) sred[w] = v;
    __syncthreads();
    int nw = (blockDim.x + 31) >> 5;
    v = (threadIdx.x < (unsigned)nw) ? sred[threadIdx.x] : 0.0f;
    if (w == 0) {
        #pragma unroll
        for (int o = 16; o > 0; o >>= 1) v += __shfl_down_sync(0xffffffffu, v, o);
    }
    __syncthreads();
    return v;
}

// ================= K1: joint chamfer tiles + fff partials =================
__global__ void __launch_bounds__(128) k_mega(const float* __restrict__ pred,
                                              const float* __restrict__ gt,
                                              const float* __restrict__ fff) {
    int bid = blockIdx.x;
    int tid = threadIdx.x;

    if (bid >= NBLK_C) {
        // ---------------- fff partial-sums block ----------------
        int fb = bid - NBLK_C;
        int b  = fb / 20;
        int m  = (fb % 20) * 128 + tid;
        float v[11];
        #pragma unroll
        for (int i = 0; i < 11; i++) v[i] = 0.0f;
        if (m < M) {
            int idx = (b * M + m) * 3;
            float E = fff[idx], F = fff[idx + 1], G = fff[idx + 2];
            float A2  = fmaxf(E * G - F * F, 0.0f);
            float A   = sqrtf(A2);
            float inv = 1.0f / (A2 + 1e-20f);
            v[0] = E;        v[1] = G;        v[2] = inv;
            v[3] = E * inv;  v[4] = E * E * inv;
            v[5] = G * inv;  v[6] = G * G * inv;
            v[7] = F * F * inv;
            float d = E - G; v[8] = d * d * inv;
            if ((b & 1) == 0) {
                int idx2 = ((b + 1) * M + m) * 3;
                float E2 = fff[idx2], F2 = fff[idx2 + 1], G2 = fff[idx2 + 2];
                float dE = E - E2, dF = F - F2, dG = G - G2;
                v[9] = dE * dE + 2.0f * dF * dF + dG * dG;
            }
            v[10] = A;
        }
        #pragma unroll
        for (int k = 0; k < 11; k++) {
            float s = blockReduceSum(v[k]);
            if (tid == 0) g_fffp[fb * 11 + k] = s;
        }
        return;
    }

    // ---------------- joint chamfer tile ----------------
    __shared__ ulonglong2 sA[CPK];        // {gx2, gy2}
    __shared__ ulonglong2 sB[CPK];        // {gz2, gn2}
    __shared__ float2     colW[4][CPK];   // per-warp col-min accumulators

    int gi = bid & (NG - 1);
    int pi = (bid >> 4) % NP;
    int b  = bid / (NG * NP);
    int w  = tid >> 5;

    // stage candidates (gt chunk gi): pack for FFMA2, norms folded
    const float* gbase = gt + (size_t)(b * N + gi * CB) * 3;
    for (int j = tid; j < CPK; j += 128) {
        const float* g = gbase + 6 * j;
        float x0 = g[0], y0 = g[1], z0 = g[2];
        float x1 = g[3], y1 = g[4], z1 = g[5];
        ulonglong2 ua, ub;
        ua.x = pack2(x0, x1);
        ua.y = pack2(y0, y1);
        ub.x = pack2(z0, z1);
        ub.y = pack2(x0 * x0 + y0 * y0 + z0 * z0,
                     x1 * x1 + y1 * y1 + z1 * z1);
        sA[j] = ua;
        sB[j] = ub;
    }
    // init col-min accumulators
    for (int j = tid; j < 4 * CPK; j += 128)
        ((float2*)colW)[j] = make_float2(BIG, BIG);

    // queries (pred chunk pi): 4 per thread, norms folded into pn2
    unsigned long long npx[4], npy[4], npz[4], pn2[4];
    float mn[4];
    int   mq[4];
    bool  val[4];
    #pragma unroll
    for (int q = 0; q < 4; q++) {
        int m = pi * QB + q * 128 + tid;
        mq[q] = m; val[q] = (m < M);
        float px = 0.f, py = 0.f, pz = 0.f, pn = BIG;
        if (val[q]) {
            const float* p = pred + (size_t)(b * M + m) * 3;
            px = p[0]; py = p[1]; pz = p[2];
            pn = px * px + py * py + pz * pz;
        }
        npx[q] = pack2(-2.f * px, -2.f * px);
        npy[q] = pack2(-2.f * py, -2.f * py);
        npz[q] = pack2(-2.f * pz, -2.f * pz);
        pn2[q] = pack2(pn, pn);
        mn[q]  = BIG;
    }
    __syncthreads();

    // main loop: each lane walks all packs, skewed so lanes hit distinct slots
    #pragma unroll 2
    for (int s = 0; s < CPK; s++) {
        int jp = (s + tid) & (CPK - 1);
        ulonglong2 ua = sA[jp];
        ulonglong2 ub = sB[jp];
        float cl, ch;
        {
            unsigned long long t = fma2(ua.x, npx[0],
                                   fma2(ua.y, npy[0],
                                   fma2(ub.x, npz[0], pn2[0])));
            t = add2(t, ub.y);
            float lo, hi; unpack2(t, lo, hi);
            mn[0] = fminf(mn[0], fminf(lo, hi));
            cl = lo; ch = hi;
        }
        #pragma unroll
        for (int q = 1; q < 4; q++) {
            unsigned long long t = fma2(ua.x, npx[q],
                                   fma2(ua.y, npy[q],
                                   fma2(ub.x, npz[q], pn2[q])));
            t = add2(t, ub.y);
            float lo, hi; unpack2(t, lo, hi);
            mn[q] = fminf(mn[q], fminf(lo, hi));
            cl = fminf(cl, lo); ch = fminf(ch, hi);
        }
        float2 cw = colW[w][jp];
        cw.x = fminf(cw.x, cl);
        cw.y = fminf(cw.y, ch);
        colW[w][jp] = cw;
    }

    // row-min partials (true d^2, both norms included)
    #pragma unroll
    for (int q = 0; q < 4; q++) {
        if (val[q]) g_partP[gi * (B * M) + b * M + mq[q]] = mn[q];
    }
    __syncthreads();

    // merge per-warp col-mins, write gt-side partials
    float2* outG = g_partG2 + pi * (B * N / 2) + (b * N + gi * CB) / 2;
    for (int j = tid; j < CPK; j += 128) {
        float2 c0 = colW[0][j], c1 = colW[1][j];
        float2 c2 = colW[2][j], c3 = colW[3][j];
        float2 r;
        r.x = fminf(fminf(c0.x, c1.x), fminf(c2.x, c3.x));
        r.y = fminf(fminf(c0.y, c1.y), fminf(c2.y, c3.y));
        outG[j] = r;
    }
}

// ================= K2: finish — min over chunks, clamp, partial sums =========
__global__ void __launch_bounds__(512) k_finish() {
    int bid = blockIdx.x;
    int tid = threadIdx.x;
    float d = 0.0f;
    if (bid < FB_P) {
        int qi = bid * 512 + tid;          // [0, B*M)
        if (qi < B * M) {
            float f = g_partP[qi];
            #pragma unroll
            for (int ch = 1; ch < NG; ch++)
                f = fminf(f, g_partP[ch * (B * M) + qi]);
            d = fmaxf(f, 0.0f);
        }
    } else {
        int gi = (bid - FB_P) * 512 + tid;  // [0, B*N/2), exact
        float2 f = g_partG2[gi];
        #pragma unroll
        for (int ch = 1; ch < NP; ch++) {
            float2 v = g_partG2[ch * (B * N / 2) + gi];
            f.x = fminf(f.x, v.x);
            f.y = fminf(f.y, v.y);
        }
        d = fmaxf(f.x, 0.0f) + fmaxf(f.y, 0.0f);
    }
    float s = blockReduceSum(d);
    if (tid == 0) g_sum2[bid] = s;
}

// ================= K3: final combine =================
__global__ void __launch_bounds__(512) k_final(const float* __restrict__ A_gt,
                                               float* __restrict__ out) {
    int tid = threadIdx.x;
    __shared__ float sA[NBLK_F];
    __shared__ float acc[12];

    #pragma unroll
    for (int k = 0; k < 10; k++) {
        float v = (tid < NBLK_F) ? g_fffp[tid * 11 + k] : 0.0f;
        float s = blockReduceSum(v);
        if (tid == 0) acc[k] = s;
    }
    {
        float v = (tid < FB_P) ? g_sum2[tid] : 0.0f;
        float s = blockReduceSum(v);
        if (tid == 0) acc[10] = s;
        v = (tid < FB_G) ? g_sum2[FB_P + tid] : 0.0f;
        s = blockReduceSum(v);
        if (tid == 0) acc[11] = s;
    }
    if (tid < NBLK_F) sA[tid] = g_fffp[tid * 11 + 10];
    __syncthreads();

    if (tid == 0) {
        float BM = (float)(B * M);
        float L_chd = acc[10] / BM + acc[11] / (float)(B * N);
        float sE = acc[0], sG = acc[1], sInv = acc[2];
        float sEinv = acc[3], sE2inv = acc[4], sGinv = acc[5], sG2inv = acc[6];
        float sF2inv = acc[7], sStretch = acc[8], sMc = acc[9];
        float mE = sE / BM, mG = sG / BM;
        float L_E  = (sE2inv - 2.0f * mE * sEinv + mE * mE * sInv) / BM;
        float L_G  = (sG2inv - 2.0f * mG * sGinv + mG * mG * sInv) / BM;
        float L_F  = sF2inv  / BM;
        float L_st = sStretch / BM;
        float L_mc = sMc / (0.5f * BM);
        float L_ol = 0.0f;
        for (int b = 0; b < B; b++) {
            float at = 0.0f;
            for (int j = 0; j < 20; j++) at += sA[b * 20 + j];
            at *= (1.0f / (float)SPP);
            float r = fmaxf(at - A_gt[b], 0.0f);
            L_ol += r * r;
        }
        L_ol *= (1.0f / (float)B);
        out[0] = L_chd + L_mc + L_F + L_E + L_G + L_st + L_ol;
    }
}

extern "C" void kernel_launch(void* const* d_in, const int* in_sizes, int n_in,
                              void* d_out, int out_size) {
    (void)in_sizes; (void)n_in; (void)out_size;
    const float* pc_gt   = (const float*)d_in[0];
    const float* pc_pred = (const float*)d_in[1];
    const float* fffp    = (const float*)d_in[2];
    const float* A_gt    = (const float*)d_in[3];
    float* out = (float*)d_out;

    k_mega  <<<NBLK_1, 128>>>(pc_pred, pc_gt, fffp);
    k_finish<<<FB_P + FB_G, 512>>>();
    k_final <<<1, 512>>>(A_gt, out);
}